// round 13
// baseline (speedup 1.0000x reference)
#include <cuda_runtime.h>
#include <cuda_fp16.h>
#include <mma.h>

using namespace nvcuda;

#define N_NODES 50000
#define N_EDGES 640000
#define HID 128
#define N_GRAPHS 512
#define AX_IN 64
#define AX_OUT 64
#define G_OUT 128
#define OUT_CH 8
#define PAD 32            // padded CSR row stride
#define OVER_CAP 8192     // overflow capacity (deg>32 edges; expected ~0)
#define N_TILES64 ((N_NODES + 63) / 64)   // 782 row tiles of 64
#define GEMM_BLOCKS 296                   // 2 per SM

typedef unsigned long long ull;

// ---------------- device scratch ----------------
__device__ int4  g_csrp4[(size_t)N_NODES * PAD / 4];  // padded CSR
__device__ int2  g_over[OVER_CAP];
__device__ int   g_over_ctr;
__device__ int4  g_dstv4[N_EDGES / 4];
__device__ int4  g_srcv4[N_EDGES / 4];
__device__ int4  g_rank4[N_EDGES / 4];
__device__ int4  g_batch4[N_NODES / 4];
__device__ int4  g_ecnt4[N_NODES / 4];   // in-degree (without self loop)
__device__ int   g_gptr[N_GRAPHS + 1];
__device__ float4 g_pooled4[N_GRAPHS * HID / 4];
// half feature buffers (float4-declared for 16B alignment)
__device__ float4 g_bufA[(size_t)N_NODES * HID / 8];
__device__ float4 g_bufB[(size_t)N_NODES * HID / 8];
__device__ float4 g_bufC[(size_t)N_NODES * HID / 8];

#define g_csrp   ((int*)g_csrp4)
#define g_dstv   ((int*)g_dstv4)
#define g_srcv   ((int*)g_srcv4)
#define g_rank   ((int*)g_rank4)
#define g_batch  ((int*)g_batch4)
#define g_ecnt   ((int*)g_ecnt4)
#define g_pooled ((float*)g_pooled4)

__device__ __forceinline__ __half* selbuf(int s) {
    return (__half*)(s == 0 ? g_bufA : (s == 1 ? g_bufB : g_bufC));
}

// ---------------- init: zero counters + convert x fp32->fp16 into bufB ----------------
__global__ void k_init(const float* __restrict__ x) {
    int stride = gridDim.x * blockDim.x;
    int i0 = blockIdx.x * blockDim.x + threadIdx.x;
    int4 z = make_int4(0, 0, 0, 0);
    for (int i = i0; i < N_NODES / 4; i += stride) g_ecnt4[i] = z;
    float4 z4 = make_float4(0.f, 0.f, 0.f, 0.f);
    for (int i = i0; i < N_GRAPHS * HID / 4; i += stride) g_pooled4[i] = z4;
    uint2* xh = (uint2*)g_bufB;
    const float4* xf = (const float4*)x;
    for (int i = i0; i < N_NODES * HID / 4; i += stride) {
        float4 v = xf[i];
        __half2 a = __floats2half2_rn(v.x, v.y);
        __half2 b = __floats2half2_rn(v.z, v.w);
        xh[i] = make_uint2(*(unsigned*)&a, *(unsigned*)&b);
    }
    if (i0 == 0) g_over_ctr = 0;
}

// ---------------- prep: dtype detect + convert + degree histogram + gptr ----------------
__global__ void k_prep(const int* __restrict__ ei, const int* __restrict__ bt) {
    __shared__ int s_is64;
    if (threadIdx.x == 0) {
        int zeros = 0;
#pragma unroll
        for (int i = 0; i < 64; i++)
            if (ei[2 * i + 1] == 0) zeros++;
        s_is64 = (zeros >= 48) ? 1 : 0;
    }
    __syncthreads();
    int is64 = s_is64;
    int t = blockIdx.x * blockDim.x + threadIdx.x;
    if (t < N_EDGES / 4) {
        int4 sv, dv;
        if (is64) {
            const longlong2* e = (const longlong2*)ei;
            longlong2 a = e[t * 2], b = e[t * 2 + 1];
            longlong2 c = e[N_EDGES / 2 + t * 2], d = e[N_EDGES / 2 + t * 2 + 1];
            sv = make_int4((int)a.x, (int)a.y, (int)b.x, (int)b.y);
            dv = make_int4((int)c.x, (int)c.y, (int)d.x, (int)d.y);
        } else {
            const int4* e = (const int4*)ei;
            sv = e[t];
            dv = e[N_EDGES / 4 + t];
        }
        g_srcv4[t] = sv;
        g_dstv4[t] = dv;
        int4 rk;
        rk.x = atomicAdd(&g_ecnt[dv.x], 1);
        rk.y = atomicAdd(&g_ecnt[dv.y], 1);
        rk.z = atomicAdd(&g_ecnt[dv.z], 1);
        rk.w = atomicAdd(&g_ecnt[dv.w], 1);
        g_rank4[t] = rk;
    }
    if (t < N_NODES / 4) {
        int4 bv;
        if (is64) {
            const longlong2* b = (const longlong2*)bt;
            longlong2 p = b[t * 2], q = b[t * 2 + 1];
            bv = make_int4((int)p.x, (int)p.y, (int)q.x, (int)q.y);
        } else {
            bv = ((const int4*)bt)[t];
        }
        g_batch4[t] = bv;
    }
    // graph boundaries from sorted batch (each gptr entry written exactly once)
    if (t < N_NODES) {
        int b = is64 ? (int)((const long long*)bt)[t] : bt[t];
        int pb = -1;
        if (t > 0) pb = is64 ? (int)((const long long*)bt)[t - 1] : bt[t - 1];
        for (int g = pb + 1; g <= b; g++) g_gptr[g] = t;
        if (t == N_NODES - 1)
            for (int g = b + 1; g <= N_GRAPHS; g++) g_gptr[g] = N_NODES;
    }
}

// ---------------- fill: padded scatter ----------------
__global__ void k_fill() {
    int t = blockIdx.x * blockDim.x + threadIdx.x;
    if (t >= N_EDGES / 4) return;
    int4 sv = g_srcv4[t];
    int4 dv = g_dstv4[t];
    int4 rk = g_rank4[t];
#pragma unroll
    for (int u = 0; u < 4; u++) {
        int s = (&sv.x)[u], d = (&dv.x)[u], r = (&rk.x)[u];
        if (r < PAD) {
            g_csrp[d * PAD + r] = s;
        } else {
            int p = atomicAdd(&g_over_ctr, 1);
            if (p < OVER_CAP) g_over[p] = make_int2(d, s);
        }
    }
}

// ---------------- GEMM via tensor cores: persistent, register B, 64-row tiles ----------------
// Y[N,128] = X[N,128] @ W[128,128]. Warp owns a fixed 16-col slice; its 8 B
// fragments (full K) live in registers. Per iteration: 64-row X tile staged in
// smem, each warp runs 4 INDEPENDENT accumulator chains (4 row-subtiles).
__global__ void k_gemm_wmma(int insel, int outsel, const float* __restrict__ Wf) {
    __shared__ __half sWh[128][136];
    __shared__ __half sX[64][136];
    __shared__ float  sAcc[8][16][16];
    const __half* X = selbuf(insel);
    __half* Y = selbuf(outsel);
    int tid = threadIdx.x, wid = tid >> 5, lane = tid & 31;

    // W fp32 -> fp16 smem (once per block)
    for (int i = tid; i < HID * HID; i += 256)
        sWh[i >> 7][i & 127] = __float2half(Wf[i]);
    __syncthreads();

    // this warp's column-slice B fragments (full K) -> registers
    wmma::fragment<wmma::matrix_b, 16, 16, 16, __half, wmma::row_major> bfr[8];
#pragma unroll
    for (int kb = 0; kb < 8; kb++)
        wmma::load_matrix_sync(bfr[kb], &sWh[kb * 16][wid * 16], 136);

    int er = lane >> 1, cb = (lane & 1) * 8;  // epilogue: row, col-chunk

    for (int tile = blockIdx.x; tile < N_TILES64; tile += gridDim.x) {
        int row0 = tile * 64;
        __syncthreads();   // previous tile's sX fully consumed
#pragma unroll
        for (int j = 0; j < 4; j++) {
            int idx = tid + j * 256;          // 1024 uint4 = 64 rows x 16 segs
            int r = idx >> 4, seg = idx & 15;
            int gr = row0 + r;
            if (gr >= N_NODES) gr = N_NODES - 1;  // clamp (tail)
            ((uint4*)&sX[r][0])[seg] = ((const uint4*)X)[(size_t)gr * 16 + seg];
        }
        __syncthreads();

        wmma::fragment<wmma::accumulator, 16, 16, 16, float> acc[4];
#pragma unroll
        for (int rt = 0; rt < 4; rt++) wmma::fill_fragment(acc[rt], 0.f);
#pragma unroll
        for (int kb = 0; kb < 8; kb++) {
#pragma unroll
            for (int rt = 0; rt < 4; rt++) {
                wmma::fragment<wmma::matrix_a, 16, 16, 16, __half, wmma::row_major> a;
                wmma::load_matrix_sync(a, &sX[rt * 16][kb * 16], 136);
                wmma::mma_sync(acc[rt], a, bfr[kb], acc[rt]);
            }
        }
#pragma unroll
        for (int rt = 0; rt < 4; rt++) {
            wmma::store_matrix_sync(&sAcc[wid][0][0], acc[rt], 16, wmma::mem_row_major);
            __syncwarp();
            int grow = row0 + rt * 16 + er;
            if (grow < N_NODES) {
                const float* src = &sAcc[wid][er][cb];
                __half2 h0 = __floats2half2_rn(src[0], src[1]);
                __half2 h1 = __floats2half2_rn(src[2], src[3]);
                __half2 h2 = __floats2half2_rn(src[4], src[5]);
                __half2 h3 = __floats2half2_rn(src[6], src[7]);
                uint4 v = make_uint4(*(unsigned*)&h0, *(unsigned*)&h1,
                                     *(unsigned*)&h2, *(unsigned*)&h3);
                ((uint4*)Y)[(((size_t)grow) * 128 + wid * 16 + cb) >> 3] = v;
            }
            __syncwarp();   // reads done before sAcc reuse
        }
    }
}

// ---------------- agg core: one node's GCN-aggregated row (warp-collective) ----------------
__device__ __forceinline__ float4 agg_row(const uint2* __restrict__ H2, int n, int lane,
                                          const float* __restrict__ bias) {
    int degn = g_ecnt[n];
    float din = rsqrtf((float)(degn + 1));
    uint2 hr = H2[(size_t)n * 32 + lane];
    __half2* hp = (__half2*)&hr;
    float2 f0 = __half22float2(hp[0]), f1 = __half22float2(hp[1]);
    float4 acc = make_float4(din * f0.x, din * f0.y, din * f1.x, din * f1.y);

    int m = degn < PAD ? degn : PAD;
    int idx = 0;
    float wgt = 0.f;
    if (lane < m) {
        idx = g_csrp[n * PAD + lane];
        wgt = rsqrtf((float)(g_ecnt[idx] + 1));
    }
    int j = 0;
    for (; j + 4 <= m; j += 4) {
        int s0 = __shfl_sync(0xffffffffu, idx, j);
        int s1 = __shfl_sync(0xffffffffu, idx, j + 1);
        int s2 = __shfl_sync(0xffffffffu, idx, j + 2);
        int s3 = __shfl_sync(0xffffffffu, idx, j + 3);
        float w0 = __shfl_sync(0xffffffffu, wgt, j);
        float w1 = __shfl_sync(0xffffffffu, wgt, j + 1);
        float w2 = __shfl_sync(0xffffffffu, wgt, j + 2);
        float w3 = __shfl_sync(0xffffffffu, wgt, j + 3);
        uint2 v0 = H2[(size_t)s0 * 32 + lane];
        uint2 v1 = H2[(size_t)s1 * 32 + lane];
        uint2 v2 = H2[(size_t)s2 * 32 + lane];
        uint2 v3 = H2[(size_t)s3 * 32 + lane];
        {
            __half2* p = (__half2*)&v0;
            float2 a = __half22float2(p[0]), b = __half22float2(p[1]);
            acc.x += w0 * a.x; acc.y += w0 * a.y; acc.z += w0 * b.x; acc.w += w0 * b.y;
        }
        {
            __half2* p = (__half2*)&v1;
            float2 a = __half22float2(p[0]), b = __half22float2(p[1]);
            acc.x += w1 * a.x; acc.y += w1 * a.y; acc.z += w1 * b.x; acc.w += w1 * b.y;
        }
        {
            __half2* p = (__half2*)&v2;
            float2 a = __half22float2(p[0]), b = __half22float2(p[1]);
            acc.x += w2 * a.x; acc.y += w2 * a.y; acc.z += w2 * b.x; acc.w += w2 * b.y;
        }
        {
            __half2* p = (__half2*)&v3;
            float2 a = __half22float2(p[0]), b = __half22float2(p[1]);
            acc.x += w3 * a.x; acc.y += w3 * a.y; acc.z += w3 * b.x; acc.w += w3 * b.y;
        }
    }
    for (; j < m; j++) {
        int s0 = __shfl_sync(0xffffffffu, idx, j);
        float w0 = __shfl_sync(0xffffffffu, wgt, j);
        uint2 v0 = H2[(size_t)s0 * 32 + lane];
        __half2* p = (__half2*)&v0;
        float2 a = __half22float2(p[0]), b = __half22float2(p[1]);
        acc.x += w0 * a.x; acc.y += w0 * a.y; acc.z += w0 * b.x; acc.w += w0 * b.y;
    }
    // overflow edges (rank >= PAD): only nodes with deg > PAD scan the list
    if (degn > PAD) {
        int oc = g_over_ctr;
        if (oc > OVER_CAP) oc = OVER_CAP;
        for (int i = 0; i < oc; i++) {
            int2 o = g_over[i];
            if (o.x == n) {
                float w = rsqrtf((float)(g_ecnt[o.y] + 1));
                uint2 v = H2[(size_t)o.y * 32 + lane];
                __half2* p = (__half2*)&v;
                float2 a = __half22float2(p[0]), b = __half22float2(p[1]);
                acc.x += w * a.x; acc.y += w * a.y; acc.z += w * b.x; acc.w += w * b.y;
            }
        }
    }
    float4 b4 = ((const float4*)bias)[lane];
    float4 o;
    o.x = fmaxf(din * acc.x + b4.x, 0.f);
    o.y = fmaxf(din * acc.y + b4.y, 0.f);
    o.z = fmaxf(din * acc.z + b4.z, 0.f);
    o.w = fmaxf(din * acc.w + b4.w, 0.f);
    return o;
}

// ---------------- agg layer 1 ----------------
__global__ void k_agg(int insel, int outsel, const float* __restrict__ bias) {
    const uint2* H2 = (const uint2*)selbuf(insel);
    __half* O = selbuf(outsel);
    int n = (blockIdx.x * blockDim.x + threadIdx.x) >> 5;
    int lane = threadIdx.x & 31;
    if (n >= N_NODES) return;
    float4 o = agg_row(H2, n, lane, bias);
    __half2 oa = __floats2half2_rn(o.x, o.y);
    __half2 ob = __floats2half2_rn(o.z, o.w);
    ((uint2*)O)[(size_t)n * 32 + lane] = make_uint2(*(unsigned*)&oa, *(unsigned*)&ob);
}

// ---------------- agg layer 2 fused with pool-sum ----------------
__global__ void k_agg_pool(int insel, const float* __restrict__ bias) {
    __shared__ float sRow[8][132];
    const uint2* H2 = (const uint2*)selbuf(insel);
    int tid = threadIdx.x;
    int wid = tid >> 5, lane = tid & 31;
    int n = blockIdx.x * 8 + wid;   // 6250*8 == N_NODES exactly
    float4 o = agg_row(H2, n, lane, bias);
    sRow[wid][lane * 4 + 0] = o.x;
    sRow[wid][lane * 4 + 1] = o.y;
    sRow[wid][lane * 4 + 2] = o.z;
    sRow[wid][lane * 4 + 3] = o.w;
    __syncthreads();
    if (tid < HID) {
        int c = tid;
        int nb = blockIdx.x * 8;
        int g = g_batch[nb];
        float acc = 0.f;
#pragma unroll
        for (int r = 0; r < 8; r++) {
            int gn = g_batch[nb + r];
            if (gn != g) {
                atomicAdd(&g_pooled[g * HID + c], acc);
                acc = 0.f;
                g = gn;
            }
            acc += sRow[r][c];
        }
        atomicAdd(&g_pooled[g * HID + c], acc);
    }
}

// ---------------- head: mean + lin1 + ax lin + concat + lin2 ----------------
__global__ void k_head(const float* __restrict__ ax,
                       const float* __restrict__ lin1W, const float* __restrict__ lin1b,
                       const float* __restrict__ axW, const float* __restrict__ axb,
                       const float* __restrict__ lin2W, const float* __restrict__ lin2b,
                       float* __restrict__ out) {
    int g = blockIdx.x;
    int t = threadIdx.x;  // 192
    __shared__ float sp[G_OUT];
    __shared__ float sa[AX_IN];
    __shared__ float z[G_OUT + AX_OUT];
    int cnt = g_gptr[g + 1] - g_gptr[g];
    float inv = 1.f / (float)(cnt > 1 ? cnt : 1);
    if (t < G_OUT) {
        sp[t] = g_pooled[g * HID + t] * inv;
    } else {
        sa[t - G_OUT] = ax[g * AX_IN + (t - G_OUT)];
    }
    __syncthreads();
    if (t < G_OUT) {
        float acc = lin1b[t];
#pragma unroll 8
        for (int k = 0; k < HID; k++) acc += sp[k] * lin1W[k * G_OUT + t];
        z[t] = acc;
    } else {
        int c = t - G_OUT;
        float acc = axb[c];
#pragma unroll 8
        for (int k = 0; k < AX_IN; k++) acc += sa[k] * axW[k * AX_OUT + c];
        z[t] = acc;
    }
    __syncthreads();
    if (t < OUT_CH) {
        float o = lin2b[t];
#pragma unroll 8
        for (int k = 0; k < G_OUT + AX_OUT; k++) o += z[k] * lin2W[k * OUT_CH + t];
        out[g * OUT_CH + t] = o;
    }
}

// ---------------- launch ----------------
extern "C" void kernel_launch(void* const* d_in, const int* in_sizes, int n_in,
                              void* d_out, int out_size) {
    const float* x     = (const float*)d_in[0];
    const int*   ei    = (const int*)d_in[1];
    const int*   bt    = (const int*)d_in[2];
    const float* ax    = (const float*)d_in[3];
    const float* W1    = (const float*)d_in[4];
    const float* b1    = (const float*)d_in[5];
    const float* W2    = (const float*)d_in[6];
    const float* b2    = (const float*)d_in[7];
    const float* lin1W = (const float*)d_in[8];
    const float* lin1b = (const float*)d_in[9];
    const float* axW   = (const float*)d_in[10];
    const float* axb   = (const float*)d_in[11];
    const float* lin2W = (const float*)d_in[12];
    const float* lin2b = (const float*)d_in[13];
    float* out = (float*)d_out;

    const int EB4 = (N_EDGES / 4 + 255) / 256;   // 625

    k_init<<<2048, 256>>>(x);                     // zero + x -> fp16 (bufB)
    k_prep<<<EB4, 256>>>(ei, bt);                 // convert + hist/rank + gptr
    k_fill<<<EB4, 256>>>();                       // padded CSR scatter
    k_gemm_wmma<<<GEMM_BLOCKS, 256>>>(1, 0, W1);  // xh(B) @ W1 -> A
    k_agg<<<(N_NODES * 32) / 256, 256>>>(0, 1, b1);   // agg(A) -> B (relu)
    k_gemm_wmma<<<GEMM_BLOCKS, 256>>>(1, 2, W2);  // B @ W2 -> C
    k_agg_pool<<<N_NODES / 8, 256>>>(2, b2);      // agg(C) + pool-sum
    k_head<<<N_GRAPHS, 192>>>(ax, lin1W, lin1b, axW, axb, lin2W, lin2b, out);
}

// round 14
// speedup vs baseline: 1.4861x; 1.4861x over previous
#include <cuda_runtime.h>
#include <cuda_fp16.h>
#include <mma.h>

using namespace nvcuda;

#define N_NODES 50000
#define N_EDGES 640000
#define HID 128
#define N_GRAPHS 512
#define AX_IN 64
#define AX_OUT 64
#define G_OUT 128
#define OUT_CH 8
#define PAD 32            // padded CSR row stride
#define OVER_CAP 8192     // overflow capacity (deg>32 edges; expected ~0)
#define N_TILES (N_NODES / 16)   // 3125 row tiles of 16 (exact)
#define GEMM_BLOCKS 592          // 4 per SM (regs/smem allow it)

typedef unsigned long long ull;

// ---------------- device scratch ----------------
__device__ int4  g_csrp4[(size_t)N_NODES * PAD / 4];  // padded CSR
__device__ int2  g_over[OVER_CAP];
__device__ int   g_over_ctr;
__device__ int4  g_dstv4[N_EDGES / 4];
__device__ int4  g_srcv4[N_EDGES / 4];
__device__ int4  g_rank4[N_EDGES / 4];
__device__ int4  g_batch4[N_NODES / 4];
__device__ int4  g_ecnt4[N_NODES / 4];   // in-degree (without self loop)
__device__ int   g_gptr[N_GRAPHS + 1];
__device__ float4 g_pooled4[N_GRAPHS * HID / 4];
// half feature buffers (float4-declared for 16B alignment)
__device__ float4 g_bufA[(size_t)N_NODES * HID / 8];
__device__ float4 g_bufB[(size_t)N_NODES * HID / 8];
__device__ float4 g_bufC[(size_t)N_NODES * HID / 8];

#define g_csrp   ((int*)g_csrp4)
#define g_dstv   ((int*)g_dstv4)
#define g_srcv   ((int*)g_srcv4)
#define g_rank   ((int*)g_rank4)
#define g_batch  ((int*)g_batch4)
#define g_ecnt   ((int*)g_ecnt4)
#define g_pooled ((float*)g_pooled4)

__device__ __forceinline__ __half* selbuf(int s) {
    return (__half*)(s == 0 ? g_bufA : (s == 1 ? g_bufB : g_bufC));
}

// ---------------- init: zero counters + convert x fp32->fp16 into bufB ----------------
__global__ void k_init(const float* __restrict__ x) {
    int stride = gridDim.x * blockDim.x;
    int i0 = blockIdx.x * blockDim.x + threadIdx.x;
    int4 z = make_int4(0, 0, 0, 0);
    for (int i = i0; i < N_NODES / 4; i += stride) g_ecnt4[i] = z;
    float4 z4 = make_float4(0.f, 0.f, 0.f, 0.f);
    for (int i = i0; i < N_GRAPHS * HID / 4; i += stride) g_pooled4[i] = z4;
    uint2* xh = (uint2*)g_bufB;
    const float4* xf = (const float4*)x;
    for (int i = i0; i < N_NODES * HID / 4; i += stride) {
        float4 v = xf[i];
        __half2 a = __floats2half2_rn(v.x, v.y);
        __half2 b = __floats2half2_rn(v.z, v.w);
        xh[i] = make_uint2(*(unsigned*)&a, *(unsigned*)&b);
    }
    if (i0 == 0) g_over_ctr = 0;
}

// ---------------- prep: dtype detect + convert + degree histogram + gptr ----------------
__global__ void k_prep(const int* __restrict__ ei, const int* __restrict__ bt) {
    __shared__ int s_is64;
    if (threadIdx.x == 0) {
        int zeros = 0;
#pragma unroll
        for (int i = 0; i < 64; i++)
            if (ei[2 * i + 1] == 0) zeros++;
        s_is64 = (zeros >= 48) ? 1 : 0;
    }
    __syncthreads();
    int is64 = s_is64;
    int t = blockIdx.x * blockDim.x + threadIdx.x;
    if (t < N_EDGES / 4) {
        int4 sv, dv;
        if (is64) {
            const longlong2* e = (const longlong2*)ei;
            longlong2 a = e[t * 2], b = e[t * 2 + 1];
            longlong2 c = e[N_EDGES / 2 + t * 2], d = e[N_EDGES / 2 + t * 2 + 1];
            sv = make_int4((int)a.x, (int)a.y, (int)b.x, (int)b.y);
            dv = make_int4((int)c.x, (int)c.y, (int)d.x, (int)d.y);
        } else {
            const int4* e = (const int4*)ei;
            sv = e[t];
            dv = e[N_EDGES / 4 + t];
        }
        g_srcv4[t] = sv;
        g_dstv4[t] = dv;
        int4 rk;
        rk.x = atomicAdd(&g_ecnt[dv.x], 1);
        rk.y = atomicAdd(&g_ecnt[dv.y], 1);
        rk.z = atomicAdd(&g_ecnt[dv.z], 1);
        rk.w = atomicAdd(&g_ecnt[dv.w], 1);
        g_rank4[t] = rk;
    }
    if (t < N_NODES / 4) {
        int4 bv;
        if (is64) {
            const longlong2* b = (const longlong2*)bt;
            longlong2 p = b[t * 2], q = b[t * 2 + 1];
            bv = make_int4((int)p.x, (int)p.y, (int)q.x, (int)q.y);
        } else {
            bv = ((const int4*)bt)[t];
        }
        g_batch4[t] = bv;
    }
    // graph boundaries from sorted batch (each gptr entry written exactly once)
    if (t < N_NODES) {
        int b = is64 ? (int)((const long long*)bt)[t] : bt[t];
        int pb = -1;
        if (t > 0) pb = is64 ? (int)((const long long*)bt)[t - 1] : bt[t - 1];
        for (int g = pb + 1; g <= b; g++) g_gptr[g] = t;
        if (t == N_NODES - 1)
            for (int g = b + 1; g <= N_GRAPHS; g++) g_gptr[g] = N_NODES;
    }
}

// ---------------- fill: padded scatter ----------------
__global__ void k_fill() {
    int t = blockIdx.x * blockDim.x + threadIdx.x;
    if (t >= N_EDGES / 4) return;
    int4 sv = g_srcv4[t];
    int4 dv = g_dstv4[t];
    int4 rk = g_rank4[t];
#pragma unroll
    for (int u = 0; u < 4; u++) {
        int s = (&sv.x)[u], d = (&dv.x)[u], r = (&rk.x)[u];
        if (r < PAD) {
            g_csrp[d * PAD + r] = s;
        } else {
            int p = atomicAdd(&g_over_ctr, 1);
            if (p < OVER_CAP) g_over[p] = make_int2(d, s);
        }
    }
}

// ---------------- GEMM via tensor cores: persistent, register-resident B ----------------
// Y[N,128] = X[N,128] @ W[128,128]. Each warp owns a fixed 16-col slice:
// its 8 B fragments (full K) load once per block and stay in registers.
// Blocks loop over 16-row tiles; X tile double-buffered (1 sync per tile).
__global__ void k_gemm_wmma(int insel, int outsel, const float* __restrict__ Wf) {
    __shared__ __half sWh[128][136];
    __shared__ __half sX[2][16][136];
    __shared__ float  sAcc[8][16][16];
    const __half* X = selbuf(insel);
    __half* Y = selbuf(outsel);
    int tid = threadIdx.x, wid = tid >> 5, lane = tid & 31;

    // W fp32 -> fp16 smem (once per block)
    for (int i = tid; i < HID * HID; i += 256)
        sWh[i >> 7][i & 127] = __float2half(Wf[i]);
    __syncthreads();

    // preload this warp's column-slice B fragments (full K) into registers
    wmma::fragment<wmma::matrix_b, 16, 16, 16, __half, wmma::row_major> bfr[8];
#pragma unroll
    for (int kb = 0; kb < 8; kb++)
        wmma::load_matrix_sync(bfr[kb], &sWh[kb * 16][wid * 16], 136);

    int r = tid >> 4, q = tid & 15;           // X-tile stage: row, uint4-seg
    int er = lane >> 1, cb = (lane & 1) * 8;  // epilogue: row, col-chunk

    int p = 0;
    for (int tile = blockIdx.x; tile < N_TILES; tile += gridDim.x, p ^= 1) {
        int row0 = tile * 16;
        // stage into bank p; compute of tile (t-2, same bank) finished before
        // each thread's stage of tile t (program order + the sync at t-1).
        ((uint4*)&sX[p][r][0])[q] = ((const uint4*)X)[(size_t)(row0 + r) * 16 + q];
        __syncthreads();

        wmma::fragment<wmma::accumulator, 16, 16, 16, float> acc;
        wmma::fill_fragment(acc, 0.f);
#pragma unroll
        for (int kb = 0; kb < 8; kb++) {
            wmma::fragment<wmma::matrix_a, 16, 16, 16, __half, wmma::row_major> a;
            wmma::load_matrix_sync(a, &sX[p][0][kb * 16], 136);
            wmma::mma_sync(acc, a, bfr[kb], acc);
        }
        wmma::store_matrix_sync(&sAcc[wid][0][0], acc, 16, wmma::mem_row_major);
        __syncwarp();
        const float* src = &sAcc[wid][er][cb];
        __half2 h0 = __floats2half2_rn(src[0], src[1]);
        __half2 h1 = __floats2half2_rn(src[2], src[3]);
        __half2 h2 = __floats2half2_rn(src[4], src[5]);
        __half2 h3 = __floats2half2_rn(src[6], src[7]);
        uint4 v = make_uint4(*(unsigned*)&h0, *(unsigned*)&h1,
                             *(unsigned*)&h2, *(unsigned*)&h3);
        ((uint4*)Y)[(((size_t)(row0 + er)) * 128 + wid * 16 + cb) >> 3] = v;
        __syncwarp();   // sAcc reads done before next tile's store
    }
}

// ---------------- agg core: one node's GCN-aggregated row (warp-collective) ----------------
__device__ __forceinline__ float4 agg_row(const uint2* __restrict__ H2, int n, int lane,
                                          const float* __restrict__ bias) {
    int degn = g_ecnt[n];
    float din = rsqrtf((float)(degn + 1));
    uint2 hr = H2[(size_t)n * 32 + lane];
    __half2* hp = (__half2*)&hr;
    float2 f0 = __half22float2(hp[0]), f1 = __half22float2(hp[1]);
    float4 acc = make_float4(din * f0.x, din * f0.y, din * f1.x, din * f1.y);

    int m = degn < PAD ? degn : PAD;
    int idx = 0;
    float wgt = 0.f;
    if (lane < m) {
        idx = g_csrp[n * PAD + lane];
        wgt = rsqrtf((float)(g_ecnt[idx] + 1));
    }
    int j = 0;
    for (; j + 4 <= m; j += 4) {
        int s0 = __shfl_sync(0xffffffffu, idx, j);
        int s1 = __shfl_sync(0xffffffffu, idx, j + 1);
        int s2 = __shfl_sync(0xffffffffu, idx, j + 2);
        int s3 = __shfl_sync(0xffffffffu, idx, j + 3);
        float w0 = __shfl_sync(0xffffffffu, wgt, j);
        float w1 = __shfl_sync(0xffffffffu, wgt, j + 1);
        float w2 = __shfl_sync(0xffffffffu, wgt, j + 2);
        float w3 = __shfl_sync(0xffffffffu, wgt, j + 3);
        uint2 v0 = H2[(size_t)s0 * 32 + lane];
        uint2 v1 = H2[(size_t)s1 * 32 + lane];
        uint2 v2 = H2[(size_t)s2 * 32 + lane];
        uint2 v3 = H2[(size_t)s3 * 32 + lane];
        {
            __half2* p = (__half2*)&v0;
            float2 a = __half22float2(p[0]), b = __half22float2(p[1]);
            acc.x += w0 * a.x; acc.y += w0 * a.y; acc.z += w0 * b.x; acc.w += w0 * b.y;
        }
        {
            __half2* p = (__half2*)&v1;
            float2 a = __half22float2(p[0]), b = __half22float2(p[1]);
            acc.x += w1 * a.x; acc.y += w1 * a.y; acc.z += w1 * b.x; acc.w += w1 * b.y;
        }
        {
            __half2* p = (__half2*)&v2;
            float2 a = __half22float2(p[0]), b = __half22float2(p[1]);
            acc.x += w2 * a.x; acc.y += w2 * a.y; acc.z += w2 * b.x; acc.w += w2 * b.y;
        }
        {
            __half2* p = (__half2*)&v3;
            float2 a = __half22float2(p[0]), b = __half22float2(p[1]);
            acc.x += w3 * a.x; acc.y += w3 * a.y; acc.z += w3 * b.x; acc.w += w3 * b.y;
        }
    }
    for (; j < m; j++) {
        int s0 = __shfl_sync(0xffffffffu, idx, j);
        float w0 = __shfl_sync(0xffffffffu, wgt, j);
        uint2 v0 = H2[(size_t)s0 * 32 + lane];
        __half2* p = (__half2*)&v0;
        float2 a = __half22float2(p[0]), b = __half22float2(p[1]);
        acc.x += w0 * a.x; acc.y += w0 * a.y; acc.z += w0 * b.x; acc.w += w0 * b.y;
    }
    // overflow edges (rank >= PAD): only nodes with deg > PAD scan the list
    if (degn > PAD) {
        int oc = g_over_ctr;
        if (oc > OVER_CAP) oc = OVER_CAP;
        for (int i = 0; i < oc; i++) {
            int2 o = g_over[i];
            if (o.x == n) {
                float w = rsqrtf((float)(g_ecnt[o.y] + 1));
                uint2 v = H2[(size_t)o.y * 32 + lane];
                __half2* p = (__half2*)&v;
                float2 a = __half22float2(p[0]), b = __half22float2(p[1]);
                acc.x += w * a.x; acc.y += w * a.y; acc.z += w * b.x; acc.w += w * b.y;
            }
        }
    }
    float4 b4 = ((const float4*)bias)[lane];
    float4 o;
    o.x = fmaxf(din * acc.x + b4.x, 0.f);
    o.y = fmaxf(din * acc.y + b4.y, 0.f);
    o.z = fmaxf(din * acc.z + b4.z, 0.f);
    o.w = fmaxf(din * acc.w + b4.w, 0.f);
    return o;
}

// ---------------- agg layer 1 ----------------
__global__ void k_agg(int insel, int outsel, const float* __restrict__ bias) {
    const uint2* H2 = (const uint2*)selbuf(insel);
    __half* O = selbuf(outsel);
    int n = (blockIdx.x * blockDim.x + threadIdx.x) >> 5;
    int lane = threadIdx.x & 31;
    if (n >= N_NODES) return;
    float4 o = agg_row(H2, n, lane, bias);
    __half2 oa = __floats2half2_rn(o.x, o.y);
    __half2 ob = __floats2half2_rn(o.z, o.w);
    ((uint2*)O)[(size_t)n * 32 + lane] = make_uint2(*(unsigned*)&oa, *(unsigned*)&ob);
}

// ---------------- agg layer 2 fused with pool-sum ----------------
__global__ void k_agg_pool(int insel, const float* __restrict__ bias) {
    __shared__ float sRow[8][132];
    const uint2* H2 = (const uint2*)selbuf(insel);
    int tid = threadIdx.x;
    int wid = tid >> 5, lane = tid & 31;
    int n = blockIdx.x * 8 + wid;   // 6250*8 == N_NODES exactly
    float4 o = agg_row(H2, n, lane, bias);
    sRow[wid][lane * 4 + 0] = o.x;
    sRow[wid][lane * 4 + 1] = o.y;
    sRow[wid][lane * 4 + 2] = o.z;
    sRow[wid][lane * 4 + 3] = o.w;
    __syncthreads();
    if (tid < HID) {
        int c = tid;
        int nb = blockIdx.x * 8;
        int g = g_batch[nb];
        float acc = 0.f;
#pragma unroll
        for (int r = 0; r < 8; r++) {
            int gn = g_batch[nb + r];
            if (gn != g) {
                atomicAdd(&g_pooled[g * HID + c], acc);
                acc = 0.f;
                g = gn;
            }
            acc += sRow[r][c];
        }
        atomicAdd(&g_pooled[g * HID + c], acc);
    }
}

// ---------------- head: mean + lin1 + ax lin + concat + lin2 ----------------
__global__ void k_head(const float* __restrict__ ax,
                       const float* __restrict__ lin1W, const float* __restrict__ lin1b,
                       const float* __restrict__ axW, const float* __restrict__ axb,
                       const float* __restrict__ lin2W, const float* __restrict__ lin2b,
                       float* __restrict__ out) {
    int g = blockIdx.x;
    int t = threadIdx.x;  // 192
    __shared__ float sp[G_OUT];
    __shared__ float sa[AX_IN];
    __shared__ float z[G_OUT + AX_OUT];
    int cnt = g_gptr[g + 1] - g_gptr[g];
    float inv = 1.f / (float)(cnt > 1 ? cnt : 1);
    if (t < G_OUT) {
        sp[t] = g_pooled[g * HID + t] * inv;
    } else {
        sa[t - G_OUT] = ax[g * AX_IN + (t - G_OUT)];
    }
    __syncthreads();
    if (t < G_OUT) {
        float acc = lin1b[t];
#pragma unroll 8
        for (int k = 0; k < HID; k++) acc += sp[k] * lin1W[k * G_OUT + t];
        z[t] = acc;
    } else {
        int c = t - G_OUT;
        float acc = axb[c];
#pragma unroll 8
        for (int k = 0; k < AX_IN; k++) acc += sa[k] * axW[k * AX_OUT + c];
        z[t] = acc;
    }
    __syncthreads();
    if (t < OUT_CH) {
        float o = lin2b[t];
#pragma unroll 8
        for (int k = 0; k < G_OUT + AX_OUT; k++) o += z[k] * lin2W[k * OUT_CH + t];
        out[g * OUT_CH + t] = o;
    }
}

// ---------------- launch ----------------
extern "C" void kernel_launch(void* const* d_in, const int* in_sizes, int n_in,
                              void* d_out, int out_size) {
    const float* x     = (const float*)d_in[0];
    const int*   ei    = (const int*)d_in[1];
    const int*   bt    = (const int*)d_in[2];
    const float* ax    = (const float*)d_in[3];
    const float* W1    = (const float*)d_in[4];
    const float* b1    = (const float*)d_in[5];
    const float* W2    = (const float*)d_in[6];
    const float* b2    = (const float*)d_in[7];
    const float* lin1W = (const float*)d_in[8];
    const float* lin1b = (const float*)d_in[9];
    const float* axW   = (const float*)d_in[10];
    const float* axb   = (const float*)d_in[11];
    const float* lin2W = (const float*)d_in[12];
    const float* lin2b = (const float*)d_in[13];
    float* out = (float*)d_out;

    const int EB4 = (N_EDGES / 4 + 255) / 256;   // 625

    k_init<<<2048, 256>>>(x);                     // zero + x -> fp16 (bufB)
    k_prep<<<EB4, 256>>>(ei, bt);                 // convert + hist/rank + gptr
    k_fill<<<EB4, 256>>>();                       // padded CSR scatter
    k_gemm_wmma<<<GEMM_BLOCKS, 256>>>(1, 0, W1);  // xh(B) @ W1 -> A
    k_agg<<<(N_NODES * 32) / 256, 256>>>(0, 1, b1);   // agg(A) -> B (relu)
    k_gemm_wmma<<<GEMM_BLOCKS, 256>>>(1, 2, W2);  // B @ W2 -> C
    k_agg_pool<<<N_NODES / 8, 256>>>(2, b2);      // agg(C) + pool-sum
    k_head<<<N_GRAPHS, 192>>>(ax, lin1W, lin1b, axW, axb, lin2W, lin2b, out);
}